// round 14
// baseline (speedup 1.0000x reference)
#include <cuda_runtime.h>
#include <cuda_fp16.h>
#include <math.h>
#include <cstdint>

// ---------------------------------------------------------------------------
// Problem constants
// ---------------------------------------------------------------------------
#define TOKENS   4096           // B*T = 2*2048
#define TSEQ     2048
#define DMODEL   1024
#define NHEADS   16
#define DHEAD    64
#define DFF      4096
#define WINDOW   256

// ---------------------------------------------------------------------------
// Scratch (device globals; no runtime allocation allowed)
// ---------------------------------------------------------------------------
__device__ __half g_xn_h  [(size_t)TOKENS * DMODEL];      // rmsnorm1 out (fp16)
__device__ __half g_qkv_h [(size_t)TOKENS * 3 * DMODEL];  // qkv (fp16)
__device__ __half g_gate_h[(size_t)TOKENS * DMODEL];      // sigmoid gate (fp16)
__device__ __half g_attn_h[(size_t)TOKENS * DMODEL];      // gated attn out (fp16)
__device__ __half g_hn_h  [(size_t)TOKENS * DMODEL];      // rmsnorm2 out (fp16)
__device__ __half g_u_h   [(size_t)TOKENS * DFF];         // silu(g)*u (fp16)
// fp16 weights
__device__ __half g_wqg [(size_t)4 * DMODEL * DMODEL];    // [qkv_w; gate_w]
__device__ __half g_wout[(size_t)DMODEL * DMODEL];
__device__ __half g_wf  [(size_t)2 * DFF * DMODEL];       // interleaved [wg_j; wu_j]
__device__ __half g_wo  [(size_t)DMODEL * DFF];

// ---------------------------------------------------------------------------
// Helpers
// ---------------------------------------------------------------------------
__device__ __forceinline__ float sigmoid_f(float x) {
    return 1.0f / (1.0f + __expf(-x));
}

__device__ __forceinline__ uint32_t smem_u32(const void* p) {
    uint32_t a;
    asm("{ .reg .u64 t; cvta.to.shared.u64 t, %1; cvt.u32.u64 %0, t; }"
        : "=r"(a) : "l"(p));
    return a;
}

__device__ __forceinline__ void cp16(uint32_t dst, const void* src) {
    asm volatile("cp.async.cg.shared.global [%0], [%1], 16;"
                 :: "r"(dst), "l"(src) : "memory");
}
#define CP_COMMIT() asm volatile("cp.async.commit_group;" ::: "memory")
#define CP_WAIT(n)  asm volatile("cp.async.wait_group %0;" :: "n"(n) : "memory")

__device__ __forceinline__ void mma_f16(float* d, const uint32_t* a, const uint32_t* b) {
    asm volatile(
        "mma.sync.aligned.m16n8k16.row.col.f32.f16.f16.f32 "
        "{%0,%1,%2,%3}, {%4,%5,%6,%7}, {%8,%9}, {%0,%1,%2,%3};"
        : "+f"(d[0]), "+f"(d[1]), "+f"(d[2]), "+f"(d[3])
        : "r"(a[0]), "r"(a[1]), "r"(a[2]), "r"(a[3]), "r"(b[0]), "r"(b[1]));
}

__device__ __forceinline__ void ldsm4(uint32_t& r0, uint32_t& r1,
                                      uint32_t& r2, uint32_t& r3, uint32_t addr) {
    asm volatile("ldmatrix.sync.aligned.m8n8.x4.shared.b16 {%0,%1,%2,%3}, [%4];"
                 : "=r"(r0), "=r"(r1), "=r"(r2), "=r"(r3) : "r"(addr));
}
__device__ __forceinline__ void ldsm4t(uint32_t& r0, uint32_t& r1,
                                       uint32_t& r2, uint32_t& r3, uint32_t addr) {
    asm volatile("ldmatrix.sync.aligned.m8n8.x4.trans.shared.b16 {%0,%1,%2,%3}, [%4];"
                 : "=r"(r0), "=r"(r1), "=r"(r2), "=r"(r3) : "r"(addr));
}

__device__ __forceinline__ uint32_t packh2(float lo, float hi) {
    __half2 h = __floats2half2_rn(lo, hi);
    return *(uint32_t*)&h;
}

// ---------------------------------------------------------------------------
// Fused prologue kernel: blocks [0, TOKENS) do rmsnorm1; the rest convert all
// six weight matrices to fp16 (wg/wu row-interleaved into g_wf), vectorized
// 4 float4 per thread (MLP=4).
// ---------------------------------------------------------------------------
#define S_QKV  786432      // 3*1024*1024/4
#define S_1M   262144      // 1024*1024/4
#define S_4M  1048576      // 4096*1024/4
#define W2H_TOT (S_QKV + 2*S_1M + 3*S_4M)   // 4456448 float4s
#define W2H_BLOCKS ((W2H_TOT / 4 + 255) / 256)   // 4352

__global__ void __launch_bounds__(256) prologue_kernel(
    const float* __restrict__ x, const float* __restrict__ ln1_w,
    __half* __restrict__ xn_out,
    const float* __restrict__ qkv_w, const float* __restrict__ gate_w,
    const float* __restrict__ out_w, const float* __restrict__ wg,
    const float* __restrict__ wu, const float* __restrict__ wo,
    __half* __restrict__ wqg, __half* __restrict__ wouth,
    __half* __restrict__ wf, __half* __restrict__ woh)
{
    int tid = threadIdx.x;
    if (blockIdx.x < TOKENS) {
        // ---- rmsnorm path ----
        __shared__ float warp_sums[8];
        int row = blockIdx.x;
        const float4* x4 = (const float4*)(x + (size_t)row * DMODEL);
        const float4* w4 = (const float4*)ln1_w;
        float4 xv = x4[tid];
        float ss = xv.x * xv.x + xv.y * xv.y + xv.z * xv.z + xv.w * xv.w;
        #pragma unroll
        for (int o = 16; o > 0; o >>= 1) ss += __shfl_xor_sync(0xffffffffu, ss, o);
        if ((tid & 31) == 0) warp_sums[tid >> 5] = ss;
        __syncthreads();
        if (tid < 8) {
            float v = warp_sums[tid];
            #pragma unroll
            for (int o = 4; o > 0; o >>= 1) v += __shfl_xor_sync(0xffu, v, o);
            if (tid == 0) warp_sums[0] = v;
        }
        __syncthreads();
        float scale = rsqrtf(warp_sums[0] * (1.0f / DMODEL) + 1e-6f);
        float4 wv = w4[tid];
        __half2 h0 = __floats2half2_rn(xv.x * scale * wv.x, xv.y * scale * wv.y);
        __half2 h1 = __floats2half2_rn(xv.z * scale * wv.z, xv.w * scale * wv.w);
        __half2* p = (__half2*)(xn_out + (size_t)row * DMODEL + tid * 4);
        p[0] = h0; p[1] = h1;
        return;
    }

    // ---- weight conversion path ----
    int iv = (blockIdx.x - TOKENS) * 256 + tid;
    if (iv >= W2H_TOT / 4) return;
    int i = iv * 4;
    const float* src;
    __half* dst;
    int l;
    size_t doff;
    if (i < S_QKV) {
        src = qkv_w; dst = wqg; l = i; doff = (size_t)l * 4;
    } else if (i < S_QKV + S_1M) {
        l = i - S_QKV;
        src = gate_w; dst = wqg + (size_t)3 * DMODEL * DMODEL;
        doff = (size_t)l * 4;
    } else if (i < S_QKV + 2 * S_1M) {
        l = i - S_QKV - S_1M;
        src = out_w; dst = wouth; doff = (size_t)l * 4;
    } else if (i < S_QKV + 2 * S_1M + S_4M) {
        l = i - S_QKV - 2 * S_1M;
        int row = l >> 8, c4 = l & 255;
        src = wg; dst = wf;
        doff = ((size_t)(2 * row)) * DMODEL + c4 * 4;
    } else if (i < S_QKV + 2 * S_1M + 2 * S_4M) {
        l = i - S_QKV - 2 * S_1M - S_4M;
        int row = l >> 8, c4 = l & 255;
        src = wu; dst = wf;
        doff = ((size_t)(2 * row + 1)) * DMODEL + c4 * 4;
    } else {
        l = i - S_QKV - 2 * S_1M - 2 * S_4M;
        src = wo; dst = woh; doff = (size_t)l * 4;
    }
    const float4* s4 = (const float4*)src;
    float4 a = s4[l], b = s4[l + 1], c = s4[l + 2], d = s4[l + 3];
    uint4 u0, u1;
    u0.x = packh2(a.x, a.y); u0.y = packh2(a.z, a.w);
    u0.z = packh2(b.x, b.y); u0.w = packh2(b.z, b.w);
    u1.x = packh2(c.x, c.y); u1.y = packh2(c.z, c.w);
    u1.z = packh2(d.x, d.y); u1.w = packh2(d.z, d.w);
    uint4* p = (uint4*)(dst + doff);
    p[0] = u0; p[1] = u1;
}

// ---------------------------------------------------------------------------
// RMSNorm (fp16 output): one block per row of 1024 floats (used for ln2)
// ---------------------------------------------------------------------------
__global__ void __launch_bounds__(256) rmsnorm_kernel(
    const float* __restrict__ x, const float* __restrict__ w,
    __half* __restrict__ out)
{
    __shared__ float warp_sums[8];
    int row = blockIdx.x;
    int tid = threadIdx.x;
    const float4* x4 = (const float4*)(x + (size_t)row * DMODEL);
    const float4* w4 = (const float4*)w;
    float4 xv = x4[tid];
    float ss = xv.x * xv.x + xv.y * xv.y + xv.z * xv.z + xv.w * xv.w;
    #pragma unroll
    for (int o = 16; o > 0; o >>= 1) ss += __shfl_xor_sync(0xffffffffu, ss, o);
    if ((tid & 31) == 0) warp_sums[tid >> 5] = ss;
    __syncthreads();
    if (tid < 8) {
        float v = warp_sums[tid];
        #pragma unroll
        for (int o = 4; o > 0; o >>= 1) v += __shfl_xor_sync(0xffu, v, o);
        if (tid == 0) warp_sums[0] = v;
    }
    __syncthreads();
    float scale = rsqrtf(warp_sums[0] * (1.0f / DMODEL) + 1e-6f);
    float4 wv = w4[tid];
    __half2 h0 = __floats2half2_rn(xv.x * scale * wv.x, xv.y * scale * wv.y);
    __half2 h1 = __floats2half2_rn(xv.z * scale * wv.z, xv.w * scale * wv.w);
    __half2* p = (__half2*)(out + (size_t)row * DMODEL + tid * 4);
    p[0] = h0; p[1] = h1;
}

// ---------------------------------------------------------------------------
// fp16 tensor-core GEMM (NT): C[M,N] = A[M,K]*B[N,K]^T, fp32 accumulate.
// CTA tile 128x256, BK=128, 256 threads / 8 warps (2x4), warp tile 64x64,
// 2-stage cp.async double buffer, ldmatrix.x4 fragment loads,
// ONE barrier per chunk (top-of-loop barrier orders buffer reuse).
// Row stride 272B (256B data + 16B pad) -> conflict-free ldmatrix.
// EPI: 4=add-aux(fp32 out) 5=qkv(fp16)/gate-sigmoid(fp16) split
//      6=FFN silu-interleave
// ---------------------------------------------------------------------------
#define ROWB   272
#define ASZ_A  (128 * ROWB)          // 34816
#define ASZ_B  (256 * ROWB)          // 69632
#define STAGEB (ASZ_A + ASZ_B)       // 104448
#define GSMEM  (2 * STAGEB)          // 208896
#define GTHREADS 256

template <int EPI>
__global__ void __launch_bounds__(GTHREADS) gemm_h(
    const __half* __restrict__ A, const __half* __restrict__ B,
    void* __restrict__ Cv, const void* __restrict__ aux,
    int M, int N, int K)
{
    extern __shared__ __align__(16) unsigned char sm[];
    uint32_t sb = smem_u32(sm);

    int tid  = threadIdx.x;
    int warp = tid >> 5;
    int lane = tid & 31;
    int g = lane >> 2;
    int t = lane & 3;
    int m0 = blockIdx.y * 128;
    int n0 = blockIdx.x * 256;
    int wm = (warp & 1) * 64;
    int wn = (warp >> 1) * 64;

    const __half* Ab = A + (size_t)m0 * K;
    const __half* Bb = B + (size_t)n0 * K;

    int lr = tid >> 4, lq = tid & 15;
    uint32_t dL = lr * ROWB + lq * 16;

    float acc[4][8][4];
    #pragma unroll
    for (int f = 0; f < 4; f++)
        #pragma unroll
        for (int n = 0; n < 8; n++)
            #pragma unroll
            for (int i = 0; i < 4; i++) acc[f][n][i] = 0.0f;

    int nch = K >> 7;

    // ---- prologue: stage 0 ----
    {
        uint32_t so = sb;
        #pragma unroll
        for (int j = 0; j < 8; j++)
            cp16(so + dL + j * 16 * ROWB,
                 Ab + (size_t)(lr + j * 16) * K + lq * 8);
        #pragma unroll
        for (int j = 0; j < 16; j++)
            cp16(so + ASZ_A + dL + j * 16 * ROWB,
                 Bb + (size_t)(lr + j * 16) * K + lq * 8);
        CP_COMMIT();
    }

    int la_r = (lane & 7) + ((lane >> 3) & 1) * 8;
    int la_c = ((lane >> 4) & 1) * 16;
    int lb_r = (lane & 7) + ((lane >> 4) & 1) * 8;
    int lb_c = ((lane >> 3) & 1) * 16;

    for (int c = 0; c < nch; c++) {
        CP_WAIT(0);
        __syncthreads();   // (a) chunk-c data visible; (b) all warps done with
                           //     the buffer about to be refilled (prev compute)

        int cur = c & 1;
        if (c + 1 < nch) {
            int k0 = (c + 1) << 7;
            uint32_t so = sb + (cur ^ 1) * STAGEB;
            #pragma unroll
            for (int j = 0; j < 8; j++)
                cp16(so + dL + j * 16 * ROWB,
                     Ab + (size_t)(lr + j * 16) * K + k0 + lq * 8);
            #pragma unroll
            for (int j = 0; j < 16; j++)
                cp16(so + ASZ_A + dL + j * 16 * ROWB,
                     Bb + (size_t)(lr + j * 16) * K + k0 + lq * 8);
            CP_COMMIT();
        }

        uint32_t sA = sb + cur * STAGEB;
        uint32_t sB = sA + ASZ_A;

        #pragma unroll
        for (int ks = 0; ks < 8; ks++) {
            int kb = ks * 32;
            uint32_t af[4][4];
            uint32_t bf[8][2];
            #pragma unroll
            for (int f = 0; f < 4; f++) {
                uint32_t addr = sA + (wm + f * 16 + la_r) * ROWB + kb + la_c;
                ldsm4(af[f][0], af[f][1], af[f][2], af[f][3], addr);
            }
            #pragma unroll
            for (int np = 0; np < 4; np++) {
                uint32_t addr = sB + (wn + np * 16 + lb_r) * ROWB + kb + lb_c;
                ldsm4(bf[2 * np][0], bf[2 * np][1],
                      bf[2 * np + 1][0], bf[2 * np + 1][1], addr);
            }
            #pragma unroll
            for (int f = 0; f < 4; f++)
                #pragma unroll
                for (int n = 0; n < 8; n++)
                    mma_f16(acc[f][n], af[f], bf[n]);
        }
        // no trailing barrier: top-of-loop barrier next iteration suffices
    }

    // ---- epilogue ----
    #pragma unroll
    for (int f = 0; f < 4; f++) {
        int rr = m0 + wm + f * 16 + g;
        #pragma unroll
        for (int n = 0; n < 8; n++) {
            int gc = n0 + wn + n * 8 + 2 * t;
            float v0 = acc[f][n][0], v1 = acc[f][n][1];
            float v2 = acc[f][n][2], v3 = acc[f][n][3];
            if (EPI == 5) {
                if (n0 >= 3 * DMODEL) {
                    int cc = gc - 3 * DMODEL;
                    __half* G = (__half*)aux;
                    *(__half2*)(G + (size_t)rr * DMODEL + cc) =
                        __floats2half2_rn(sigmoid_f(v0), sigmoid_f(v1));
                    *(__half2*)(G + (size_t)(rr + 8) * DMODEL + cc) =
                        __floats2half2_rn(sigmoid_f(v2), sigmoid_f(v3));
                } else {
                    __half* Q = (__half*)Cv;
                    *(__half2*)(Q + (size_t)rr * (3 * DMODEL) + gc)       = __floats2half2_rn(v0, v1);
                    *(__half2*)(Q + (size_t)(rr + 8) * (3 * DMODEL) + gc) = __floats2half2_rn(v2, v3);
                }
            } else if (EPI == 6) {
                int j = ((n0 + wn + n * 8) >> 1) + t;
                __half* C = (__half*)Cv;
                C[(size_t)rr * DFF + j]       = __float2half(v0 * sigmoid_f(v0) * v1);
                C[(size_t)(rr + 8) * DFF + j] = __float2half(v2 * sigmoid_f(v2) * v3);
            } else {  // EPI == 4
                size_t i0 = (size_t)rr * N + gc;
                size_t i1 = (size_t)(rr + 8) * N + gc;
                const float* ax = (const float*)aux;
                float2 x0 = *(const float2*)(ax + i0);
                float2 x1 = *(const float2*)(ax + i1);
                float* C = (float*)Cv;
                *(float2*)(C + i0) = make_float2(v0 + x0.x, v1 + x0.y);
                *(float2*)(C + i1) = make_float2(v2 + x1.x, v3 + x1.y);
            }
        }
    }
}

// ---------------------------------------------------------------------------
// Tensor-core flash attention, sliding window, fused gate (fp16).
// 256 threads / 8 warps, 128 q-rows per block, per-warp K-tile skipping,
// triple-buffered K/V (one barrier per tile), Q pre-scaled by 1/8 (bit-exact
// power-of-2), interior-tile fast path (no mask predicates).
// smem: Q[128x72h]=18432B | {K,V}[3 bufs][64x72h]=6x9216B. Total 73728B.
// ---------------------------------------------------------------------------
#define ATT_SMEM 73728

__global__ void __launch_bounds__(256) attn_mma_kernel(
    const __half* __restrict__ qkv, const __half* __restrict__ gate,
    __half* __restrict__ out)
{
    extern __shared__ __align__(16) unsigned char asm_[];
    uint32_t qbase = smem_u32(asm_);

    int tid = threadIdx.x;
    int warp = tid >> 5, lane = tid & 31;
    int g = lane >> 2, t = lane & 3;
    int b = blockIdx.y >> 4, h = blockIdx.y & 15;
    int q0 = blockIdx.x * 128;
    int wm16 = warp * 16;

    // stage Q tile [128 x 64]: 1024 quads, 4 per thread
    {
        int r = tid >> 1;
        int c = (tid & 1) * 4;
        const __half* src = qkv + ((size_t)(b * TSEQ + q0 + r)) * (3 * DMODEL) + h * DHEAD + c * 8;
        uint32_t dst = qbase + r * 144 + c * 16;
        #pragma unroll
        for (int j = 0; j < 4; j++) cp16(dst + j * 16, src + j * 8);
    }

    int s_lo = q0 - WINDOW;
    if (s_lo < 0) s_lo = 0;
    int nt = (q0 + 64 - s_lo) / 64 + 1;

    auto loadKV = [&](int s, int buf) {
        uint32_t kb = qbase + 18432 + buf * 18432;
        uint32_t vb = kb + 9216;
        int r = tid >> 2;
        int cq = (tid & 3) * 2;
        size_t base = ((size_t)(b * TSEQ + s + r)) * (3 * DMODEL) + h * DHEAD + cq * 8;
        uint32_t dK = kb + r * 144 + cq * 16;
        uint32_t dV = vb + r * 144 + cq * 16;
        #pragma unroll
        for (int j = 0; j < 2; j++) {
            cp16(dK + j * 16, qkv + base + DMODEL + j * 8);
            cp16(dV + j * 16, qkv + base + 2 * DMODEL + j * 8);
        }
    };

    loadKV(s_lo, 0);
    CP_COMMIT();

    int la_r = (lane & 7) + ((lane >> 3) & 1) * 8;
    int la_c = ((lane >> 4) & 1) * 8;
    int lb_r = (lane & 7) + ((lane >> 4) & 1) * 8;
    int lb_c = ((lane >> 3) & 1) * 8;

    uint32_t qf[4][4];
    float oacc[8][4];
    #pragma unroll
    for (int n = 0; n < 8; n++)
        #pragma unroll
        for (int i = 0; i < 4; i++) oacc[n][i] = 0.0f;
    float m0 = -1e30f, m1 = -1e30f, l0 = 0.0f, l1 = 0.0f;
    int qi0 = q0 + wm16 + g;
    int qi1 = qi0 + 8;
    int w_lo = q0 + wm16;
    int w_hi = w_lo + 15;

    int buf = 0;
    for (int it = 0; it < nt; it++) {
        int s = s_lo + it * 64;
        if (it + 1 < nt) {
            int nb = buf + 1 == 3 ? 0 : buf + 1;
            loadKV(s + 64, nb);
            CP_COMMIT();
            CP_WAIT(1);
        } else {
            CP_WAIT(0);
        }
        __syncthreads();

        if (it == 0) {
            // load Q fragments and pre-scale by 1/8 (power of 2: bit-exact)
            const __half2 qs = __floats2half2_rn(0.125f, 0.125f);
            #pragma unroll
            for (int ks = 0; ks < 4; ks++) {
                uint32_t addr = qbase + ((wm16 + la_r) * 72 + ks * 16 + la_c) * 2;
                ldsm4(qf[ks][0], qf[ks][1], qf[ks][2], qf[ks][3], addr);
                #pragma unroll
                for (int i = 0; i < 4; i++) {
                    __half2 v = __hmul2(*(__half2*)&qf[ks][i], qs);
                    qf[ks][i] = *(uint32_t*)&v;
                }
            }
        }

        uint32_t kbase = qbase + 18432 + buf * 18432;
        uint32_t vbase = kbase + 9216;
        buf = buf + 1 == 3 ? 0 : buf + 1;

        // per-warp tile skip
        if (s > w_hi || s + 63 < w_lo - (WINDOW - 1)) continue;

        float sacc[8][4];
        #pragma unroll
        for (int n = 0; n < 8; n++)
            #pragma unroll
            for (int i = 0; i < 4; i++) sacc[n][i] = 0.0f;

        #pragma unroll
        for (int ks = 0; ks < 4; ks++) {
            uint32_t bf[8][2];
            #pragma unroll
            for (int np = 0; np < 4; np++) {
                uint32_t addr = kbase + ((np * 16 + lb_r) * 72 + ks * 16 + lb_c) * 2;
                ldsm4(bf[2 * np][0], bf[2 * np][1],
                      bf[2 * np + 1][0], bf[2 * np + 1][1], addr);
            }
            #pragma unroll
            for (int nf = 0; nf < 8; nf++)
                mma_f16(sacc[nf], qf[ks], bf[nf]);
        }

        // interior tile: every (q,key) distance provably in [0, WINDOW)
        bool interior = (s <= w_lo - 63) && (s > w_hi - WINDOW);

        float mt0 = -1e30f, mt1 = -1e30f;
        if (interior) {
            #pragma unroll
            for (int nf = 0; nf < 8; nf++) {
                mt0 = fmaxf(mt0, fmaxf(sacc[nf][0], sacc[nf][1]));
                mt1 = fmaxf(mt1, fmaxf(sacc[nf][2], sacc[nf][3]));
            }
        } else {
            #pragma unroll
            for (int nf = 0; nf < 8; nf++) {
                int key = s + nf * 8 + 2 * t;
                #pragma unroll
                for (int c = 0; c < 2; c++) {
                    unsigned d0 = (unsigned)(qi0 - (key + c));
                    unsigned d1 = (unsigned)(qi1 - (key + c));
                    float v0 = (d0 < (unsigned)WINDOW) ? sacc[nf][c]     : -1e30f;
                    float v1 = (d1 < (unsigned)WINDOW) ? sacc[nf][c + 2] : -1e30f;
                    sacc[nf][c] = v0; sacc[nf][c + 2] = v1;
                    mt0 = fmaxf(mt0, v0); mt1 = fmaxf(mt1, v1);
                }
            }
        }
        mt0 = fmaxf(mt0, __shfl_xor_sync(0xffffffffu, mt0, 1));
        mt0 = fmaxf(mt0, __shfl_xor_sync(0xffffffffu, mt0, 2));
        mt1 = fmaxf(mt1, __shfl_xor_sync(0xffffffffu, mt1, 1));
        mt1 = fmaxf(mt1, __shfl_xor_sync(0xffffffffu, mt1, 2));

        float mn0 = fmaxf(m0, mt0), mn1 = fmaxf(m1, mt1);
        float cor0 = __expf(m0 - mn0), cor1 = __expf(m1 - mn1);
        m0 = mn0; m1 = mn1;
        l0 *= cor0; l1 *= cor1;
        #pragma unroll
        for (int nf = 0; nf < 8; nf++) {
            oacc[nf][0] *= cor0; oacc[nf][1] *= cor0;
            oacc[nf][2] *= cor1; oacc[nf][3] *= cor1;
        }
        float ps0 = 0.0f, ps1 = 0.0f;
        #pragma unroll
        for (int nf = 0; nf < 8; nf++) {
            #pragma unroll
            for (int c = 0; c < 2; c++) {
                float p0 = __expf(sacc[nf][c] - m0);
                float p1 = __expf(sacc[nf][c + 2] - m1);
                sacc[nf][c] = p0; sacc[nf][c + 2] = p1;
                ps0 += p0; ps1 += p1;
            }
        }
        l0 += ps0; l1 += ps1;

        #pragma unroll
        for (int kc = 0; kc < 4; kc++) {
            uint32_t pf[4];
            pf[0] = packh2(sacc[2 * kc][0],     sacc[2 * kc][1]);
            pf[1] = packh2(sacc[2 * kc][2],     sacc[2 * kc][3]);
            pf[2] = packh2(sacc[2 * kc + 1][0], sacc[2 * kc + 1][1]);
            pf[3] = packh2(sacc[2 * kc + 1][2], sacc[2 * kc + 1][3]);
            #pragma unroll
            for (int dp = 0; dp < 4; dp++) {
                uint32_t addr = vbase + ((kc * 16 + la_r) * 72 + dp * 16 + la_c) * 2;
                uint32_t v0, v1, v2, v3;
                ldsm4t(v0, v1, v2, v3, addr);
                uint32_t bb0[2] = { v0, v1 };
                uint32_t bb1[2] = { v2, v3 };
                mma_f16(oacc[2 * dp], pf, bb0);
                mma_f16(oacc[2 * dp + 1], pf, bb1);
            }
        }
    }

    l0 += __shfl_xor_sync(0xffffffffu, l0, 1);
    l0 += __shfl_xor_sync(0xffffffffu, l0, 2);
    l1 += __shfl_xor_sync(0xffffffffu, l1, 1);
    l1 += __shfl_xor_sync(0xffffffffu, l1, 2);
    float inv0 = 1.0f / l0, inv1 = 1.0f / l1;

    size_t tq0 = (size_t)b * TSEQ + qi0;
    size_t tq1 = tq0 + 8;
    #pragma unroll
    for (int nf = 0; nf < 8; nf++) {
        int col = h * DHEAD + nf * 8 + 2 * t;
        float2 g0 = __half22float2(*(const __half2*)(gate + tq0 * DMODEL + col));
        float2 g1 = __half22float2(*(const __half2*)(gate + tq1 * DMODEL + col));
        *(__half2*)(out + tq0 * DMODEL + col) =
            __floats2half2_rn(oacc[nf][0] * inv0 * g0.x, oacc[nf][1] * inv0 * g0.y);
        *(__half2*)(out + tq1 * DMODEL + col) =
            __floats2half2_rn(oacc[nf][2] * inv1 * g1.x, oacc[nf][3] * inv1 * g1.y);
    }
}

// ---------------------------------------------------------------------------
// Launch
// ---------------------------------------------------------------------------
extern "C" void kernel_launch(void* const* d_in, const int* in_sizes, int n_in,
                              void* d_out, int out_size)
{
    const float* x      = (const float*)d_in[0];
    const float* ln1_w  = (const float*)d_in[1];
    const float* qkv_w  = (const float*)d_in[2];
    const float* gate_w = (const float*)d_in[3];
    const float* out_w  = (const float*)d_in[4];
    const float* ln2_w  = (const float*)d_in[5];
    const float* wg     = (const float*)d_in[6];
    const float* wu     = (const float*)d_in[7];
    const float* wo     = (const float*)d_in[8];
    float* out = (float*)d_out;

    __half *xnh, *qkvh, *gateh, *attnh, *hnh, *ubh, *wqg, *wouth, *wfh, *woh;
    cudaGetSymbolAddress((void**)&xnh,   g_xn_h);
    cudaGetSymbolAddress((void**)&qkvh,  g_qkv_h);
    cudaGetSymbolAddress((void**)&gateh, g_gate_h);
    cudaGetSymbolAddress((void**)&attnh, g_attn_h);
    cudaGetSymbolAddress((void**)&hnh,   g_hn_h);
    cudaGetSymbolAddress((void**)&ubh,   g_u_h);
    cudaGetSymbolAddress((void**)&wqg,   g_wqg);
    cudaGetSymbolAddress((void**)&wouth, g_wout);
    cudaGetSymbolAddress((void**)&wfh,   g_wf);
    cudaGetSymbolAddress((void**)&woh,   g_wo);

    cudaFuncSetAttribute(gemm_h<4>, cudaFuncAttributeMaxDynamicSharedMemorySize, GSMEM);
    cudaFuncSetAttribute(gemm_h<5>, cudaFuncAttributeMaxDynamicSharedMemorySize, GSMEM);
    cudaFuncSetAttribute(gemm_h<6>, cudaFuncAttributeMaxDynamicSharedMemorySize, GSMEM);
    cudaFuncSetAttribute(attn_mma_kernel, cudaFuncAttributeMaxDynamicSharedMemorySize, ATT_SMEM);

    // 0+1. fused prologue: rmsnorm1 (blocks 0..4095) + all weights->fp16
    prologue_kernel<<<TOKENS + W2H_BLOCKS, 256>>>(
        x, ln1_w, xnh, qkv_w, gate_w, out_w, wg, wu, wo,
        wqg, wouth, wfh, woh);

    // 2+3. fused qkv|gate GEMM (BN=256): qkv -> fp16, gate -> sigmoid fp16
    gemm_h<5><<<dim3(4 * DMODEL / 256, TOKENS / 128), GTHREADS, GSMEM>>>(
        xnh, wqg, qkvh, gateh, TOKENS, 4 * DMODEL, DMODEL);

    // 4. attn (tensor-core flash, triple-buffered K/V) -> fp16
    attn_mma_kernel<<<dim3(TSEQ / 128, 2 * NHEADS), 256, ATT_SMEM>>>(qkvh, gateh, attnh);

    // 5. x1 = x + attn @ out_w^T -> d_out (fp32)
    gemm_h<4><<<dim3(DMODEL / 256, TOKENS / 128), GTHREADS, GSMEM>>>(
        attnh, wouth, out, x, TOKENS, DMODEL, DMODEL);

    // 6. hn = rmsnorm(x1, ln2_w) -> fp16
    rmsnorm_kernel<<<TOKENS, 256>>>(out, ln2_w, hnh);

    // 7+8. fused FFN: ub = silu(hn@wg^T) * (hn@wu^T) -> fp16 (interleaved B)
    gemm_h<6><<<dim3(2 * DFF / 256, TOKENS / 128), GTHREADS, GSMEM>>>(
        hnh, wfh, ubh, nullptr, TOKENS, 2 * DFF, DMODEL);

    // 9. out = x1 + ub @ wo^T (in-place residual on d_out)
    gemm_h<4><<<dim3(DMODEL / 256, TOKENS / 128), GTHREADS, GSMEM>>>(
        ubh, woh, out, out, TOKENS, DMODEL, DFF);
}

// round 15
// speedup vs baseline: 1.0005x; 1.0005x over previous
#include <cuda_runtime.h>
#include <cuda_fp16.h>
#include <math.h>
#include <cstdint>

// ---------------------------------------------------------------------------
// Problem constants
// ---------------------------------------------------------------------------
#define TOKENS   4096           // B*T = 2*2048
#define TSEQ     2048
#define DMODEL   1024
#define NHEADS   16
#define DHEAD    64
#define DFF      4096
#define WINDOW   256

// ---------------------------------------------------------------------------
// Scratch (device globals; no runtime allocation allowed)
// ---------------------------------------------------------------------------
__device__ __half g_xn_h  [(size_t)TOKENS * DMODEL];      // rmsnorm1 out (fp16)
__device__ __half g_qkv_h [(size_t)TOKENS * 3 * DMODEL];  // qkv (fp16; q pre-scaled by 1/8)
__device__ __half g_gate_h[(size_t)TOKENS * DMODEL];      // sigmoid gate (fp16)
__device__ __half g_attn_h[(size_t)TOKENS * DMODEL];      // gated attn out (fp16)
__device__ __half g_hn_h  [(size_t)TOKENS * DMODEL];      // rmsnorm2 out (fp16)
__device__ __half g_u_h   [(size_t)TOKENS * DFF];         // silu(g)*u (fp16)
// fp16 weights
__device__ __half g_wqg [(size_t)4 * DMODEL * DMODEL];    // [qkv_w; gate_w]
__device__ __half g_wout[(size_t)DMODEL * DMODEL];
__device__ __half g_wf  [(size_t)2 * DFF * DMODEL];       // interleaved [wg_j; wu_j]
__device__ __half g_wo  [(size_t)DMODEL * DFF];

// ---------------------------------------------------------------------------
// Helpers
// ---------------------------------------------------------------------------
__device__ __forceinline__ float sigmoid_f(float x) {
    return 1.0f / (1.0f + __expf(-x));
}

__device__ __forceinline__ uint32_t smem_u32(const void* p) {
    uint32_t a;
    asm("{ .reg .u64 t; cvta.to.shared.u64 t, %1; cvt.u32.u64 %0, t; }"
        : "=r"(a) : "l"(p));
    return a;
}

__device__ __forceinline__ void cp16(uint32_t dst, const void* src) {
    asm volatile("cp.async.cg.shared.global [%0], [%1], 16;"
                 :: "r"(dst), "l"(src) : "memory");
}
#define CP_COMMIT() asm volatile("cp.async.commit_group;" ::: "memory")
#define CP_WAIT(n)  asm volatile("cp.async.wait_group %0;" :: "n"(n) : "memory")

__device__ __forceinline__ void mma_f16(float* d, const uint32_t* a, const uint32_t* b) {
    asm volatile(
        "mma.sync.aligned.m16n8k16.row.col.f32.f16.f16.f32 "
        "{%0,%1,%2,%3}, {%4,%5,%6,%7}, {%8,%9}, {%0,%1,%2,%3};"
        : "+f"(d[0]), "+f"(d[1]), "+f"(d[2]), "+f"(d[3])
        : "r"(a[0]), "r"(a[1]), "r"(a[2]), "r"(a[3]), "r"(b[0]), "r"(b[1]));
}

__device__ __forceinline__ void ldsm4(uint32_t& r0, uint32_t& r1,
                                      uint32_t& r2, uint32_t& r3, uint32_t addr) {
    asm volatile("ldmatrix.sync.aligned.m8n8.x4.shared.b16 {%0,%1,%2,%3}, [%4];"
                 : "=r"(r0), "=r"(r1), "=r"(r2), "=r"(r3) : "r"(addr));
}
__device__ __forceinline__ void ldsm4t(uint32_t& r0, uint32_t& r1,
                                       uint32_t& r2, uint32_t& r3, uint32_t addr) {
    asm volatile("ldmatrix.sync.aligned.m8n8.x4.trans.shared.b16 {%0,%1,%2,%3}, [%4];"
                 : "=r"(r0), "=r"(r1), "=r"(r2), "=r"(r3) : "r"(addr));
}

__device__ __forceinline__ uint32_t packh2(float lo, float hi) {
    __half2 h = __floats2half2_rn(lo, hi);
    return *(uint32_t*)&h;
}

// ---------------------------------------------------------------------------
// Fused prologue kernel: blocks [0, TOKENS) do rmsnorm1; the rest convert all
// six weight matrices to fp16 (wg/wu row-interleaved into g_wf), vectorized
// 4 float4 per thread (MLP=4).
// ---------------------------------------------------------------------------
#define S_QKV  786432      // 3*1024*1024/4
#define S_1M   262144      // 1024*1024/4
#define S_4M  1048576      // 4096*1024/4
#define W2H_TOT (S_QKV + 2*S_1M + 3*S_4M)   // 4456448 float4s
#define W2H_BLOCKS ((W2H_TOT / 4 + 255) / 256)   // 4352

__global__ void __launch_bounds__(256) prologue_kernel(
    const float* __restrict__ x, const float* __restrict__ ln1_w,
    __half* __restrict__ xn_out,
    const float* __restrict__ qkv_w, const float* __restrict__ gate_w,
    const float* __restrict__ out_w, const float* __restrict__ wg,
    const float* __restrict__ wu, const float* __restrict__ wo,
    __half* __restrict__ wqg, __half* __restrict__ wouth,
    __half* __restrict__ wf, __half* __restrict__ woh)
{
    int tid = threadIdx.x;
    if (blockIdx.x < TOKENS) {
        // ---- rmsnorm path ----
        __shared__ float warp_sums[8];
        int row = blockIdx.x;
        const float4* x4 = (const float4*)(x + (size_t)row * DMODEL);
        const float4* w4 = (const float4*)ln1_w;
        float4 xv = x4[tid];
        float ss = xv.x * xv.x + xv.y * xv.y + xv.z * xv.z + xv.w * xv.w;
        #pragma unroll
        for (int o = 16; o > 0; o >>= 1) ss += __shfl_xor_sync(0xffffffffu, ss, o);
        if ((tid & 31) == 0) warp_sums[tid >> 5] = ss;
        __syncthreads();
        if (tid < 8) {
            float v = warp_sums[tid];
            #pragma unroll
            for (int o = 4; o > 0; o >>= 1) v += __shfl_xor_sync(0xffu, v, o);
            if (tid == 0) warp_sums[0] = v;
        }
        __syncthreads();
        float scale = rsqrtf(warp_sums[0] * (1.0f / DMODEL) + 1e-6f);
        float4 wv = w4[tid];
        __half2 h0 = __floats2half2_rn(xv.x * scale * wv.x, xv.y * scale * wv.y);
        __half2 h1 = __floats2half2_rn(xv.z * scale * wv.z, xv.w * scale * wv.w);
        __half2* p = (__half2*)(xn_out + (size_t)row * DMODEL + tid * 4);
        p[0] = h0; p[1] = h1;
        return;
    }

    // ---- weight conversion path ----
    int iv = (blockIdx.x - TOKENS) * 256 + tid;
    if (iv >= W2H_TOT / 4) return;
    int i = iv * 4;
    const float* src;
    __half* dst;
    int l;
    size_t doff;
    if (i < S_QKV) {
        src = qkv_w; dst = wqg; l = i; doff = (size_t)l * 4;
    } else if (i < S_QKV + S_1M) {
        l = i - S_QKV;
        src = gate_w; dst = wqg + (size_t)3 * DMODEL * DMODEL;
        doff = (size_t)l * 4;
    } else if (i < S_QKV + 2 * S_1M) {
        l = i - S_QKV - S_1M;
        src = out_w; dst = wouth; doff = (size_t)l * 4;
    } else if (i < S_QKV + 2 * S_1M + S_4M) {
        l = i - S_QKV - 2 * S_1M;
        int row = l >> 8, c4 = l & 255;
        src = wg; dst = wf;
        doff = ((size_t)(2 * row)) * DMODEL + c4 * 4;
    } else if (i < S_QKV + 2 * S_1M + 2 * S_4M) {
        l = i - S_QKV - 2 * S_1M - S_4M;
        int row = l >> 8, c4 = l & 255;
        src = wu; dst = wf;
        doff = ((size_t)(2 * row + 1)) * DMODEL + c4 * 4;
    } else {
        l = i - S_QKV - 2 * S_1M - 2 * S_4M;
        src = wo; dst = woh; doff = (size_t)l * 4;
    }
    const float4* s4 = (const float4*)src;
    float4 a = s4[l], b = s4[l + 1], c = s4[l + 2], d = s4[l + 3];
    uint4 u0, u1;
    u0.x = packh2(a.x, a.y); u0.y = packh2(a.z, a.w);
    u0.z = packh2(b.x, b.y); u0.w = packh2(b.z, b.w);
    u1.x = packh2(c.x, c.y); u1.y = packh2(c.z, c.w);
    u1.z = packh2(d.x, d.y); u1.w = packh2(d.z, d.w);
    uint4* p = (uint4*)(dst + doff);
    p[0] = u0; p[1] = u1;
}

// ---------------------------------------------------------------------------
// RMSNorm (fp16 output): one block per row of 1024 floats (used for ln2)
// ---------------------------------------------------------------------------
__global__ void __launch_bounds__(256) rmsnorm_kernel(
    const float* __restrict__ x, const float* __restrict__ w,
    __half* __restrict__ out)
{
    __shared__ float warp_sums[8];
    int row = blockIdx.x;
    int tid = threadIdx.x;
    const float4* x4 = (const float4*)(x + (size_t)row * DMODEL);
    const float4* w4 = (const float4*)w;
    float4 xv = x4[tid];
    float ss = xv.x * xv.x + xv.y * xv.y + xv.z * xv.z + xv.w * xv.w;
    #pragma unroll
    for (int o = 16; o > 0; o >>= 1) ss += __shfl_xor_sync(0xffffffffu, ss, o);
    if ((tid & 31) == 0) warp_sums[tid >> 5] = ss;
    __syncthreads();
    if (tid < 8) {
        float v = warp_sums[tid];
        #pragma unroll
        for (int o = 4; o > 0; o >>= 1) v += __shfl_xor_sync(0xffu, v, o);
        if (tid == 0) warp_sums[0] = v;
    }
    __syncthreads();
    float scale = rsqrtf(warp_sums[0] * (1.0f / DMODEL) + 1e-6f);
    float4 wv = w4[tid];
    __half2 h0 = __floats2half2_rn(xv.x * scale * wv.x, xv.y * scale * wv.y);
    __half2 h1 = __floats2half2_rn(xv.z * scale * wv.z, xv.w * scale * wv.w);
    __half2* p = (__half2*)(out + (size_t)row * DMODEL + tid * 4);
    p[0] = h0; p[1] = h1;
}

// ---------------------------------------------------------------------------
// fp16 tensor-core GEMM (NT): C[M,N] = A[M,K]*B[N,K]^T, fp32 accumulate.
// CTA tile 128x256, BK=128, 256 threads / 8 warps (2x4), warp tile 64x64,
// 2-stage cp.async double buffer, ldmatrix.x4 fragment loads.
// Row stride 272B (256B data + 16B pad) -> conflict-free ldmatrix.
// EPI: 4=add-aux(fp32 out) 5=qkv(fp16, q cols pre-scaled 1/8)/gate-sigmoid
//      6=FFN silu-interleave
// ---------------------------------------------------------------------------
#define ROWB   272
#define ASZ_A  (128 * ROWB)          // 34816
#define ASZ_B  (256 * ROWB)          // 69632
#define STAGEB (ASZ_A + ASZ_B)       // 104448
#define GSMEM  (2 * STAGEB)          // 208896
#define GTHREADS 256

template <int EPI>
__global__ void __launch_bounds__(GTHREADS) gemm_h(
    const __half* __restrict__ A, const __half* __restrict__ B,
    void* __restrict__ Cv, const void* __restrict__ aux,
    int M, int N, int K)
{
    extern __shared__ __align__(16) unsigned char sm[];
    uint32_t sb = smem_u32(sm);

    int tid  = threadIdx.x;
    int warp = tid >> 5;
    int lane = tid & 31;
    int g = lane >> 2;
    int t = lane & 3;
    int m0 = blockIdx.y * 128;
    int n0 = blockIdx.x * 256;
    int wm = (warp & 1) * 64;
    int wn = (warp >> 1) * 64;

    const __half* Ab = A + (size_t)m0 * K;
    const __half* Bb = B + (size_t)n0 * K;

    int lr = tid >> 4, lq = tid & 15;
    uint32_t dL = lr * ROWB + lq * 16;

    float acc[4][8][4];
    #pragma unroll
    for (int f = 0; f < 4; f++)
        #pragma unroll
        for (int n = 0; n < 8; n++)
            #pragma unroll
            for (int i = 0; i < 4; i++) acc[f][n][i] = 0.0f;

    int nch = K >> 7;

    // ---- prologue: stage 0 ----
    {
        uint32_t so = sb;
        #pragma unroll
        for (int j = 0; j < 8; j++)
            cp16(so + dL + j * 16 * ROWB,
                 Ab + (size_t)(lr + j * 16) * K + lq * 8);
        #pragma unroll
        for (int j = 0; j < 16; j++)
            cp16(so + ASZ_A + dL + j * 16 * ROWB,
                 Bb + (size_t)(lr + j * 16) * K + lq * 8);
        CP_COMMIT();
    }

    int la_r = (lane & 7) + ((lane >> 3) & 1) * 8;
    int la_c = ((lane >> 4) & 1) * 16;
    int lb_r = (lane & 7) + ((lane >> 4) & 1) * 8;
    int lb_c = ((lane >> 3) & 1) * 16;

    for (int c = 0; c < nch; c++) {
        CP_WAIT(0);
        __syncthreads();

        int cur = c & 1;
        if (c + 1 < nch) {
            int k0 = (c + 1) << 7;
            uint32_t so = sb + (cur ^ 1) * STAGEB;
            #pragma unroll
            for (int j = 0; j < 8; j++)
                cp16(so + dL + j * 16 * ROWB,
                     Ab + (size_t)(lr + j * 16) * K + k0 + lq * 8);
            #pragma unroll
            for (int j = 0; j < 16; j++)
                cp16(so + ASZ_A + dL + j * 16 * ROWB,
                     Bb + (size_t)(lr + j * 16) * K + k0 + lq * 8);
            CP_COMMIT();
        }

        uint32_t sA = sb + cur * STAGEB;
        uint32_t sB = sA + ASZ_A;

        #pragma unroll
        for (int ks = 0; ks < 8; ks++) {
            int kb = ks * 32;
            uint32_t af[4][4];
            uint32_t bf[8][2];
            #pragma unroll
            for (int f = 0; f < 4; f++) {
                uint32_t addr = sA + (wm + f * 16 + la_r) * ROWB + kb + la_c;
                ldsm4(af[f][0], af[f][1], af[f][2], af[f][3], addr);
            }
            #pragma unroll
            for (int np = 0; np < 4; np++) {
                uint32_t addr = sB + (wn + np * 16 + lb_r) * ROWB + kb + lb_c;
                ldsm4(bf[2 * np][0], bf[2 * np][1],
                      bf[2 * np + 1][0], bf[2 * np + 1][1], addr);
            }
            #pragma unroll
            for (int f = 0; f < 4; f++)
                #pragma unroll
                for (int n = 0; n < 8; n++)
                    mma_f16(acc[f][n], af[f], bf[n]);
        }
        __syncthreads();
    }

    // ---- epilogue ----
    // EPI==5: q columns (n0 < DMODEL, CTA-uniform) pre-scaled by 1/8 (exact
    // power-of-2 in fp32) so attention needs no softmax scaling.
    float qscale = (EPI == 5 && n0 < DMODEL) ? 0.125f : 1.0f;
    #pragma unroll
    for (int f = 0; f < 4; f++) {
        int rr = m0 + wm + f * 16 + g;
        #pragma unroll
        for (int n = 0; n < 8; n++) {
            int gc = n0 + wn + n * 8 + 2 * t;
            float v0 = acc[f][n][0], v1 = acc[f][n][1];
            float v2 = acc[f][n][2], v3 = acc[f][n][3];
            if (EPI == 5) {
                if (n0 >= 3 * DMODEL) {
                    int cc = gc - 3 * DMODEL;
                    __half* G = (__half*)aux;
                    *(__half2*)(G + (size_t)rr * DMODEL + cc) =
                        __floats2half2_rn(sigmoid_f(v0), sigmoid_f(v1));
                    *(__half2*)(G + (size_t)(rr + 8) * DMODEL + cc) =
                        __floats2half2_rn(sigmoid_f(v2), sigmoid_f(v3));
                } else {
                    __half* Q = (__half*)Cv;
                    *(__half2*)(Q + (size_t)rr * (3 * DMODEL) + gc) =
                        __floats2half2_rn(v0 * qscale, v1 * qscale);
                    *(__half2*)(Q + (size_t)(rr + 8) * (3 * DMODEL) + gc) =
                        __floats2half2_rn(v2 * qscale, v3 * qscale);
                }
            } else if (EPI == 6) {
                int j = ((n0 + wn + n * 8) >> 1) + t;
                __half* C = (__half*)Cv;
                C[(size_t)rr * DFF + j]       = __float2half(v0 * sigmoid_f(v0) * v1);
                C[(size_t)(rr + 8) * DFF + j] = __float2half(v2 * sigmoid_f(v2) * v3);
            } else {  // EPI == 4
                size_t i0 = (size_t)rr * N + gc;
                size_t i1 = (size_t)(rr + 8) * N + gc;
                const float* ax = (const float*)aux;
                float2 x0 = *(const float2*)(ax + i0);
                float2 x1 = *(const float2*)(ax + i1);
                float* C = (float*)Cv;
                *(float2*)(C + i0) = make_float2(v0 + x0.x, v1 + x0.y);
                *(float2*)(C + i1) = make_float2(v2 + x1.x, v3 + x1.y);
            }
        }
    }
}

// ---------------------------------------------------------------------------
// Tensor-core flash attention, sliding window, fused gate (fp16).
// 256 threads / 8 warps, 128 q-rows per block, per-warp K-tile skipping,
// triple-buffered K/V (one barrier per tile). Q comes in pre-scaled by 1/8,
// so the masked-softmax path has no scale multiply.
// smem: Q[128x72h]=18432B | {K,V}[3 bufs][64x72h]=6x9216B. Total 73728B.
// ---------------------------------------------------------------------------
#define ATT_SMEM 73728

__global__ void __launch_bounds__(256) attn_mma_kernel(
    const __half* __restrict__ qkv, const __half* __restrict__ gate,
    __half* __restrict__ out)
{
    extern __shared__ __align__(16) unsigned char asm_[];
    uint32_t qbase = smem_u32(asm_);

    int tid = threadIdx.x;
    int warp = tid >> 5, lane = tid & 31;
    int g = lane >> 2, t = lane & 3;
    int b = blockIdx.y >> 4, h = blockIdx.y & 15;
    int q0 = blockIdx.x * 128;
    int wm16 = warp * 16;

    // stage Q tile [128 x 64]: 1024 quads, 4 per thread
    {
        int r = tid >> 1;
        int c = (tid & 1) * 4;
        const __half* src = qkv + ((size_t)(b * TSEQ + q0 + r)) * (3 * DMODEL) + h * DHEAD + c * 8;
        uint32_t dst = qbase + r * 144 + c * 16;
        #pragma unroll
        for (int j = 0; j < 4; j++) cp16(dst + j * 16, src + j * 8);
    }

    int s_lo = q0 - WINDOW;
    if (s_lo < 0) s_lo = 0;
    int nt = (q0 + 64 - s_lo) / 64 + 1;    // tiles covering [s_lo, q0+64]

    auto loadKV = [&](int s, int buf) {
        uint32_t kb = qbase + 18432 + buf * 18432;
        uint32_t vb = kb + 9216;
        int r = tid >> 2;
        int cq = (tid & 3) * 2;
        size_t base = ((size_t)(b * TSEQ + s + r)) * (3 * DMODEL) + h * DHEAD + cq * 8;
        uint32_t dK = kb + r * 144 + cq * 16;
        uint32_t dV = vb + r * 144 + cq * 16;
        #pragma unroll
        for (int j = 0; j < 2; j++) {
            cp16(dK + j * 16, qkv + base + DMODEL + j * 8);
            cp16(dV + j * 16, qkv + base + 2 * DMODEL + j * 8);
        }
    };

    // prologue: Q + tile 0 in one group
    loadKV(s_lo, 0);
    CP_COMMIT();

    int la_r = (lane & 7) + ((lane >> 3) & 1) * 8;
    int la_c = ((lane >> 4) & 1) * 8;
    int lb_r = (lane & 7) + ((lane >> 4) & 1) * 8;
    int lb_c = ((lane >> 3) & 1) * 8;

    uint32_t qf[4][4];
    float oacc[8][4];
    #pragma unroll
    for (int n = 0; n < 8; n++)
        #pragma unroll
        for (int i = 0; i < 4; i++) oacc[n][i] = 0.0f;
    float m0 = -1e30f, m1 = -1e30f, l0 = 0.0f, l1 = 0.0f;
    int qi0 = q0 + wm16 + g;
    int qi1 = qi0 + 8;
    int w_lo = q0 + wm16;
    int w_hi = w_lo + 15;

    int buf = 0;        // buffer of tile `it`
    for (int it = 0; it < nt; it++) {
        int s = s_lo + it * 64;
        // issue next tile into buf+1 (mod 3): safe — readers of that buffer
        // finished >= 2 syncs ago (triple buffering).
        if (it + 1 < nt) {
            int nb = buf + 1 == 3 ? 0 : buf + 1;
            loadKV(s + 64, nb);
            CP_COMMIT();
            CP_WAIT(1);             // current tile's group complete
        } else {
            CP_WAIT(0);
        }
        __syncthreads();            // single barrier per tile

        if (it == 0) {
            #pragma unroll
            for (int ks = 0; ks < 4; ks++) {
                uint32_t addr = qbase + ((wm16 + la_r) * 72 + ks * 16 + la_c) * 2;
                ldsm4(qf[ks][0], qf[ks][1], qf[ks][2], qf[ks][3], addr);
            }
        }

        uint32_t kbase = qbase + 18432 + buf * 18432;
        uint32_t vbase = kbase + 9216;
        buf = buf + 1 == 3 ? 0 : buf + 1;

        // per-warp tile skip
        if (s > w_hi || s + 63 < w_lo - (WINDOW - 1)) continue;

        float sacc[8][4];
        #pragma unroll
        for (int n = 0; n < 8; n++)
            #pragma unroll
            for (int i = 0; i < 4; i++) sacc[n][i] = 0.0f;

        #pragma unroll
        for (int ks = 0; ks < 4; ks++) {
            uint32_t bf[8][2];
            #pragma unroll
            for (int np = 0; np < 4; np++) {
                uint32_t addr = kbase + ((np * 16 + lb_r) * 72 + ks * 16 + lb_c) * 2;
                ldsm4(bf[2 * np][0], bf[2 * np][1],
                      bf[2 * np + 1][0], bf[2 * np + 1][1], addr);
            }
            #pragma unroll
            for (int nf = 0; nf < 8; nf++)
                mma_f16(sacc[nf], qf[ks], bf[nf]);
        }

        // masked softmax (scores already scaled: q was pre-scaled by 1/8)
        float mt0 = -1e30f, mt1 = -1e30f;
        #pragma unroll
        for (int nf = 0; nf < 8; nf++) {
            int key = s + nf * 8 + 2 * t;
            #pragma unroll
            for (int c = 0; c < 2; c++) {
                unsigned d0 = (unsigned)(qi0 - (key + c));
                unsigned d1 = (unsigned)(qi1 - (key + c));
                float v0 = (d0 < (unsigned)WINDOW) ? sacc[nf][c]     : -1e30f;
                float v1 = (d1 < (unsigned)WINDOW) ? sacc[nf][c + 2] : -1e30f;
                sacc[nf][c] = v0; sacc[nf][c + 2] = v1;
                mt0 = fmaxf(mt0, v0); mt1 = fmaxf(mt1, v1);
            }
        }
        mt0 = fmaxf(mt0, __shfl_xor_sync(0xffffffffu, mt0, 1));
        mt0 = fmaxf(mt0, __shfl_xor_sync(0xffffffffu, mt0, 2));
        mt1 = fmaxf(mt1, __shfl_xor_sync(0xffffffffu, mt1, 1));
        mt1 = fmaxf(mt1, __shfl_xor_sync(0xffffffffu, mt1, 2));

        float mn0 = fmaxf(m0, mt0), mn1 = fmaxf(m1, mt1);
        float cor0 = __expf(m0 - mn0), cor1 = __expf(m1 - mn1);
        m0 = mn0; m1 = mn1;
        l0 *= cor0; l1 *= cor1;
        #pragma unroll
        for (int nf = 0; nf < 8; nf++) {
            oacc[nf][0] *= cor0; oacc[nf][1] *= cor0;
            oacc[nf][2] *= cor1; oacc[nf][3] *= cor1;
        }
        float ps0 = 0.0f, ps1 = 0.0f;
        #pragma unroll
        for (int nf = 0; nf < 8; nf++) {
            #pragma unroll
            for (int c = 0; c < 2; c++) {
                float p0 = __expf(sacc[nf][c] - m0);
                float p1 = __expf(sacc[nf][c + 2] - m1);
                sacc[nf][c] = p0; sacc[nf][c + 2] = p1;
                ps0 += p0; ps1 += p1;
            }
        }
        l0 += ps0; l1 += ps1;

        #pragma unroll
        for (int kc = 0; kc < 4; kc++) {
            uint32_t pf[4];
            pf[0] = packh2(sacc[2 * kc][0],     sacc[2 * kc][1]);
            pf[1] = packh2(sacc[2 * kc][2],     sacc[2 * kc][3]);
            pf[2] = packh2(sacc[2 * kc + 1][0], sacc[2 * kc + 1][1]);
            pf[3] = packh2(sacc[2 * kc + 1][2], sacc[2 * kc + 1][3]);
            #pragma unroll
            for (int dp = 0; dp < 4; dp++) {
                uint32_t addr = vbase + ((kc * 16 + la_r) * 72 + dp * 16 + la_c) * 2;
                uint32_t v0, v1, v2, v3;
                ldsm4t(v0, v1, v2, v3, addr);
                uint32_t bb0[2] = { v0, v1 };
                uint32_t bb1[2] = { v2, v3 };
                mma_f16(oacc[2 * dp], pf, bb0);
                mma_f16(oacc[2 * dp + 1], pf, bb1);
            }
        }
    }

    l0 += __shfl_xor_sync(0xffffffffu, l0, 1);
    l0 += __shfl_xor_sync(0xffffffffu, l0, 2);
    l1 += __shfl_xor_sync(0xffffffffu, l1, 1);
    l1 += __shfl_xor_sync(0xffffffffu, l1, 2);
    float inv0 = 1.0f / l0, inv1 = 1.0f / l1;

    size_t tq0 = (size_t)b * TSEQ + qi0;
    size_t tq1 = tq0 + 8;
    #pragma unroll
    for (int nf = 0; nf < 8; nf++) {
        int col = h * DHEAD + nf * 8 + 2 * t;
        float2 g0 = __half22float2(*(const __half2*)(gate + tq0 * DMODEL + col));
        float2 g1 = __half22float2(*(const __half2*)(gate + tq1 * DMODEL + col));
        *(__half2*)(out + tq0 * DMODEL + col) =
            __floats2half2_rn(oacc[nf][0] * inv0 * g0.x, oacc[nf][1] * inv0 * g0.y);
        *(__half2*)(out + tq1 * DMODEL + col) =
            __floats2half2_rn(oacc[nf][2] * inv1 * g1.x, oacc[nf][3] * inv1 * g1.y);
    }
}

// ---------------------------------------------------------------------------
// Launch
// ---------------------------------------------------------------------------
extern "C" void kernel_launch(void* const* d_in, const int* in_sizes, int n_in,
                              void* d_out, int out_size)
{
    const float* x      = (const float*)d_in[0];
    const float* ln1_w  = (const float*)d_in[1];
    const float* qkv_w  = (const float*)d_in[2];
    const float* gate_w = (const float*)d_in[3];
    const float* out_w  = (const float*)d_in[4];
    const float* ln2_w  = (const float*)d_in[5];
    const float* wg     = (const float*)d_in[6];
    const float* wu     = (const float*)d_in[7];
    const float* wo     = (const float*)d_in[8];
    float* out = (float*)d_out;

    __half *xnh, *qkvh, *gateh, *attnh, *hnh, *ubh, *wqg, *wouth, *wfh, *woh;
    cudaGetSymbolAddress((void**)&xnh,   g_xn_h);
    cudaGetSymbolAddress((void**)&qkvh,  g_qkv_h);
    cudaGetSymbolAddress((void**)&gateh, g_gate_h);
    cudaGetSymbolAddress((void**)&attnh, g_attn_h);
    cudaGetSymbolAddress((void**)&hnh,   g_hn_h);
    cudaGetSymbolAddress((void**)&ubh,   g_u_h);
    cudaGetSymbolAddress((void**)&wqg,   g_wqg);
    cudaGetSymbolAddress((void**)&wouth, g_wout);
    cudaGetSymbolAddress((void**)&wfh,   g_wf);
    cudaGetSymbolAddress((void**)&woh,   g_wo);

    cudaFuncSetAttribute(gemm_h<4>, cudaFuncAttributeMaxDynamicSharedMemorySize, GSMEM);
    cudaFuncSetAttribute(gemm_h<5>, cudaFuncAttributeMaxDynamicSharedMemorySize, GSMEM);
    cudaFuncSetAttribute(gemm_h<6>, cudaFuncAttributeMaxDynamicSharedMemorySize, GSMEM);
    cudaFuncSetAttribute(attn_mma_kernel, cudaFuncAttributeMaxDynamicSharedMemorySize, ATT_SMEM);

    // 0+1. fused prologue: rmsnorm1 (blocks 0..4095) + all weights->fp16
    prologue_kernel<<<TOKENS + W2H_BLOCKS, 256>>>(
        x, ln1_w, xnh, qkv_w, gate_w, out_w, wg, wu, wo,
        wqg, wouth, wfh, woh);

    // 2+3. fused qkv|gate GEMM (BN=256): qkv -> fp16 (q pre-scaled), gate -> sigmoid fp16
    gemm_h<5><<<dim3(4 * DMODEL / 256, TOKENS / 128), GTHREADS, GSMEM>>>(
        xnh, wqg, qkvh, gateh, TOKENS, 4 * DMODEL, DMODEL);

    // 4. attn (tensor-core flash, triple-buffered K/V) -> fp16
    attn_mma_kernel<<<dim3(TSEQ / 128, 2 * NHEADS), 256, ATT_SMEM>>>(qkvh, gateh, attnh);

    // 5. x1 = x + attn @ out_w^T -> d_out (fp32)
    gemm_h<4><<<dim3(DMODEL / 256, TOKENS / 128), GTHREADS, GSMEM>>>(
        attnh, wouth, out, x, TOKENS, DMODEL, DMODEL);

    // 6. hn = rmsnorm(x1, ln2_w) -> fp16
    rmsnorm_kernel<<<TOKENS, 256>>>(out, ln2_w, hnh);

    // 7+8. fused FFN: ub = silu(hn@wg^T) * (hn@wu^T) -> fp16 (interleaved B)
    gemm_h<6><<<dim3(2 * DFF / 256, TOKENS / 128), GTHREADS, GSMEM>>>(
        hnh, wfh, ubh, nullptr, TOKENS, 2 * DFF, DMODEL);

    // 9. out = x1 + ub @ wo^T (in-place residual on d_out)
    gemm_h<4><<<dim3(DMODEL / 256, TOKENS / 128), GTHREADS, GSMEM>>>(
        ubh, woh, out, out, TOKENS, DMODEL, DFF);
}

// round 16
// speedup vs baseline: 1.0113x; 1.0109x over previous
#include <cuda_runtime.h>
#include <cuda_fp16.h>
#include <math.h>
#include <cstdint>

// ---------------------------------------------------------------------------
// Problem constants
// ---------------------------------------------------------------------------
#define TOKENS   4096           // B*T = 2*2048
#define TSEQ     2048
#define DMODEL   1024
#define NHEADS   16
#define DHEAD    64
#define DFF      4096
#define WINDOW   256

// ---------------------------------------------------------------------------
// Scratch (device globals; no runtime allocation allowed)
// ---------------------------------------------------------------------------
__device__ __half g_xn_h  [(size_t)TOKENS * DMODEL];      // rmsnorm1 out (fp16)
__device__ __half g_qkv_h [(size_t)TOKENS * 3 * DMODEL];  // qkv (fp16)
__device__ __half g_gate_h[(size_t)TOKENS * DMODEL];      // sigmoid gate (fp16)
__device__ __half g_attn_h[(size_t)TOKENS * DMODEL];      // gated attn out (fp16)
__device__ __half g_hn_h  [(size_t)TOKENS * DMODEL];      // rmsnorm2 out (fp16)
__device__ __half g_u_h   [(size_t)TOKENS * DFF];         // silu(g)*u (fp16)
// fp16 weights
__device__ __half g_wqg [(size_t)4 * DMODEL * DMODEL];    // [qkv_w; gate_w]
__device__ __half g_wout[(size_t)DMODEL * DMODEL];
__device__ __half g_wf  [(size_t)2 * DFF * DMODEL];       // interleaved [wg_j; wu_j]
__device__ __half g_wo  [(size_t)DMODEL * DFF];

// ---------------------------------------------------------------------------
// Helpers
// ---------------------------------------------------------------------------
__device__ __forceinline__ float sigmoid_f(float x) {
    return 1.0f / (1.0f + __expf(-x));
}

__device__ __forceinline__ uint32_t smem_u32(const void* p) {
    uint32_t a;
    asm("{ .reg .u64 t; cvta.to.shared.u64 t, %1; cvt.u32.u64 %0, t; }"
        : "=r"(a) : "l"(p));
    return a;
}

__device__ __forceinline__ void cp16(uint32_t dst, const void* src) {
    asm volatile("cp.async.cg.shared.global [%0], [%1], 16;"
                 :: "r"(dst), "l"(src) : "memory");
}
#define CP_COMMIT() asm volatile("cp.async.commit_group;" ::: "memory")
#define CP_WAIT(n)  asm volatile("cp.async.wait_group %0;" :: "n"(n) : "memory")

__device__ __forceinline__ void mma_f16(float* d, const uint32_t* a, const uint32_t* b) {
    asm volatile(
        "mma.sync.aligned.m16n8k16.row.col.f32.f16.f16.f32 "
        "{%0,%1,%2,%3}, {%4,%5,%6,%7}, {%8,%9}, {%0,%1,%2,%3};"
        : "+f"(d[0]), "+f"(d[1]), "+f"(d[2]), "+f"(d[3])
        : "r"(a[0]), "r"(a[1]), "r"(a[2]), "r"(a[3]), "r"(b[0]), "r"(b[1]));
}

__device__ __forceinline__ void ldsm4(uint32_t& r0, uint32_t& r1,
                                      uint32_t& r2, uint32_t& r3, uint32_t addr) {
    asm volatile("ldmatrix.sync.aligned.m8n8.x4.shared.b16 {%0,%1,%2,%3}, [%4];"
                 : "=r"(r0), "=r"(r1), "=r"(r2), "=r"(r3) : "r"(addr));
}
__device__ __forceinline__ void ldsm4t(uint32_t& r0, uint32_t& r1,
                                       uint32_t& r2, uint32_t& r3, uint32_t addr) {
    asm volatile("ldmatrix.sync.aligned.m8n8.x4.trans.shared.b16 {%0,%1,%2,%3}, [%4];"
                 : "=r"(r0), "=r"(r1), "=r"(r2), "=r"(r3) : "r"(addr));
}

__device__ __forceinline__ uint32_t packh2(float lo, float hi) {
    __half2 h = __floats2half2_rn(lo, hi);
    return *(uint32_t*)&h;
}

// ---------------------------------------------------------------------------
// Fused prologue kernel: blocks [0, TOKENS) do rmsnorm1; the rest convert all
// six weight matrices to fp16 (wg/wu row-interleaved into g_wf), vectorized
// 4 float4 per thread (MLP=4).
// ---------------------------------------------------------------------------
#define S_QKV  786432      // 3*1024*1024/4
#define S_1M   262144      // 1024*1024/4
#define S_4M  1048576      // 4096*1024/4
#define W2H_TOT (S_QKV + 2*S_1M + 3*S_4M)   // 4456448 float4s
#define W2H_BLOCKS ((W2H_TOT / 4 + 255) / 256)   // 4352

__global__ void __launch_bounds__(256) prologue_kernel(
    const float* __restrict__ x, const float* __restrict__ ln1_w,
    __half* __restrict__ xn_out,
    const float* __restrict__ qkv_w, const float* __restrict__ gate_w,
    const float* __restrict__ out_w, const float* __restrict__ wg,
    const float* __restrict__ wu, const float* __restrict__ wo,
    __half* __restrict__ wqg, __half* __restrict__ wouth,
    __half* __restrict__ wf, __half* __restrict__ woh)
{
    int tid = threadIdx.x;
    if (blockIdx.x < TOKENS) {
        // ---- rmsnorm path ----
        __shared__ float warp_sums[8];
        int row = blockIdx.x;
        const float4* x4 = (const float4*)(x + (size_t)row * DMODEL);
        const float4* w4 = (const float4*)ln1_w;
        float4 xv = x4[tid];
        float ss = xv.x * xv.x + xv.y * xv.y + xv.z * xv.z + xv.w * xv.w;
        #pragma unroll
        for (int o = 16; o > 0; o >>= 1) ss += __shfl_xor_sync(0xffffffffu, ss, o);
        if ((tid & 31) == 0) warp_sums[tid >> 5] = ss;
        __syncthreads();
        if (tid < 8) {
            float v = warp_sums[tid];
            #pragma unroll
            for (int o = 4; o > 0; o >>= 1) v += __shfl_xor_sync(0xffu, v, o);
            if (tid == 0) warp_sums[0] = v;
        }
        __syncthreads();
        float scale = rsqrtf(warp_sums[0] * (1.0f / DMODEL) + 1e-6f);
        float4 wv = w4[tid];
        __half2 h0 = __floats2half2_rn(xv.x * scale * wv.x, xv.y * scale * wv.y);
        __half2 h1 = __floats2half2_rn(xv.z * scale * wv.z, xv.w * scale * wv.w);
        __half2* p = (__half2*)(xn_out + (size_t)row * DMODEL + tid * 4);
        p[0] = h0; p[1] = h1;
        return;
    }

    // ---- weight conversion path ----
    int iv = (blockIdx.x - TOKENS) * 256 + tid;
    if (iv >= W2H_TOT / 4) return;
    int i = iv * 4;
    const float* src;
    __half* dst;
    int l;
    size_t doff;
    if (i < S_QKV) {
        src = qkv_w; dst = wqg; l = i; doff = (size_t)l * 4;
    } else if (i < S_QKV + S_1M) {
        l = i - S_QKV;
        src = gate_w; dst = wqg + (size_t)3 * DMODEL * DMODEL;
        doff = (size_t)l * 4;
    } else if (i < S_QKV + 2 * S_1M) {
        l = i - S_QKV - S_1M;
        src = out_w; dst = wouth; doff = (size_t)l * 4;
    } else if (i < S_QKV + 2 * S_1M + S_4M) {
        l = i - S_QKV - 2 * S_1M;
        int row = l >> 8, c4 = l & 255;
        src = wg; dst = wf;
        doff = ((size_t)(2 * row)) * DMODEL + c4 * 4;
    } else if (i < S_QKV + 2 * S_1M + 2 * S_4M) {
        l = i - S_QKV - 2 * S_1M - S_4M;
        int row = l >> 8, c4 = l & 255;
        src = wu; dst = wf;
        doff = ((size_t)(2 * row + 1)) * DMODEL + c4 * 4;
    } else {
        l = i - S_QKV - 2 * S_1M - 2 * S_4M;
        src = wo; dst = woh; doff = (size_t)l * 4;
    }
    const float4* s4 = (const float4*)src;
    float4 a = s4[l], b = s4[l + 1], c = s4[l + 2], d = s4[l + 3];
    uint4 u0, u1;
    u0.x = packh2(a.x, a.y); u0.y = packh2(a.z, a.w);
    u0.z = packh2(b.x, b.y); u0.w = packh2(b.z, b.w);
    u1.x = packh2(c.x, c.y); u1.y = packh2(c.z, c.w);
    u1.z = packh2(d.x, d.y); u1.w = packh2(d.z, d.w);
    uint4* p = (uint4*)(dst + doff);
    p[0] = u0; p[1] = u1;
}

// ---------------------------------------------------------------------------
// RMSNorm (fp16 output): one block per row of 1024 floats (used for ln2)
// ---------------------------------------------------------------------------
__global__ void __launch_bounds__(256) rmsnorm_kernel(
    const float* __restrict__ x, const float* __restrict__ w,
    __half* __restrict__ out)
{
    __shared__ float warp_sums[8];
    int row = blockIdx.x;
    int tid = threadIdx.x;
    const float4* x4 = (const float4*)(x + (size_t)row * DMODEL);
    const float4* w4 = (const float4*)w;
    float4 xv = x4[tid];
    float ss = xv.x * xv.x + xv.y * xv.y + xv.z * xv.z + xv.w * xv.w;
    #pragma unroll
    for (int o = 16; o > 0; o >>= 1) ss += __shfl_xor_sync(0xffffffffu, ss, o);
    if ((tid & 31) == 0) warp_sums[tid >> 5] = ss;
    __syncthreads();
    if (tid < 8) {
        float v = warp_sums[tid];
        #pragma unroll
        for (int o = 4; o > 0; o >>= 1) v += __shfl_xor_sync(0xffu, v, o);
        if (tid == 0) warp_sums[0] = v;
    }
    __syncthreads();
    float scale = rsqrtf(warp_sums[0] * (1.0f / DMODEL) + 1e-6f);
    float4 wv = w4[tid];
    __half2 h0 = __floats2half2_rn(xv.x * scale * wv.x, xv.y * scale * wv.y);
    __half2 h1 = __floats2half2_rn(xv.z * scale * wv.z, xv.w * scale * wv.w);
    __half2* p = (__half2*)(out + (size_t)row * DMODEL + tid * 4);
    p[0] = h0; p[1] = h1;
}

// ---------------------------------------------------------------------------
// fp16 tensor-core GEMM (NT): C[M,N] = A[M,K]*B[N,K]^T, fp32 accumulate.
// CTA tile 128x256, BK=128, 256 threads / 8 warps (2x4), warp tile 64x64,
// 2-stage cp.async double buffer, ldmatrix.x4 fragment loads.
// Row stride 272B (256B data + 16B pad) -> conflict-free ldmatrix.
// EPI: 4=add-aux(fp32 out) 5=qkv(fp16)/gate-sigmoid(fp16) split
//      6=FFN silu-interleave
// ---------------------------------------------------------------------------
#define ROWB   272
#define ASZ_A  (128 * ROWB)          // 34816
#define ASZ_B  (256 * ROWB)          // 69632
#define STAGEB (ASZ_A + ASZ_B)       // 104448
#define GSMEM  (2 * STAGEB)          // 208896
#define GTHREADS 256

template <int EPI>
__global__ void __launch_bounds__(GTHREADS) gemm_h(
    const __half* __restrict__ A, const __half* __restrict__ B,
    void* __restrict__ Cv, const void* __restrict__ aux,
    int M, int N, int K)
{
    extern __shared__ __align__(16) unsigned char sm[];
    uint32_t sb = smem_u32(sm);

    int tid  = threadIdx.x;
    int warp = tid >> 5;
    int lane = tid & 31;
    int g = lane >> 2;
    int t = lane & 3;
    int m0 = blockIdx.y * 128;
    int n0 = blockIdx.x * 256;
    int wm = (warp & 1) * 64;
    int wn = (warp >> 1) * 64;

    const __half* Ab = A + (size_t)m0 * K;
    const __half* Bb = B + (size_t)n0 * K;

    int lr = tid >> 4, lq = tid & 15;
    uint32_t dL = lr * ROWB + lq * 16;

    float acc[4][8][4];
    #pragma unroll
    for (int f = 0; f < 4; f++)
        #pragma unroll
        for (int n = 0; n < 8; n++)
            #pragma unroll
            for (int i = 0; i < 4; i++) acc[f][n][i] = 0.0f;

    int nch = K >> 7;

    // ---- prologue: stage 0 ----
    {
        uint32_t so = sb;
        #pragma unroll
        for (int j = 0; j < 8; j++)
            cp16(so + dL + j * 16 * ROWB,
                 Ab + (size_t)(lr + j * 16) * K + lq * 8);
        #pragma unroll
        for (int j = 0; j < 16; j++)
            cp16(so + ASZ_A + dL + j * 16 * ROWB,
                 Bb + (size_t)(lr + j * 16) * K + lq * 8);
        CP_COMMIT();
    }

    int la_r = (lane & 7) + ((lane >> 3) & 1) * 8;
    int la_c = ((lane >> 4) & 1) * 16;
    int lb_r = (lane & 7) + ((lane >> 4) & 1) * 8;
    int lb_c = ((lane >> 3) & 1) * 16;

    for (int c = 0; c < nch; c++) {
        CP_WAIT(0);
        __syncthreads();

        int cur = c & 1;
        if (c + 1 < nch) {
            int k0 = (c + 1) << 7;
            uint32_t so = sb + (cur ^ 1) * STAGEB;
            #pragma unroll
            for (int j = 0; j < 8; j++)
                cp16(so + dL + j * 16 * ROWB,
                     Ab + (size_t)(lr + j * 16) * K + k0 + lq * 8);
            #pragma unroll
            for (int j = 0; j < 16; j++)
                cp16(so + ASZ_A + dL + j * 16 * ROWB,
                     Bb + (size_t)(lr + j * 16) * K + k0 + lq * 8);
            CP_COMMIT();
        }

        uint32_t sA = sb + cur * STAGEB;
        uint32_t sB = sA + ASZ_A;

        #pragma unroll
        for (int ks = 0; ks < 8; ks++) {
            int kb = ks * 32;
            uint32_t af[4][4];
            uint32_t bf[8][2];
            #pragma unroll
            for (int f = 0; f < 4; f++) {
                uint32_t addr = sA + (wm + f * 16 + la_r) * ROWB + kb + la_c;
                ldsm4(af[f][0], af[f][1], af[f][2], af[f][3], addr);
            }
            #pragma unroll
            for (int np = 0; np < 4; np++) {
                uint32_t addr = sB + (wn + np * 16 + lb_r) * ROWB + kb + lb_c;
                ldsm4(bf[2 * np][0], bf[2 * np][1],
                      bf[2 * np + 1][0], bf[2 * np + 1][1], addr);
            }
            #pragma unroll
            for (int f = 0; f < 4; f++)
                #pragma unroll
                for (int n = 0; n < 8; n++)
                    mma_f16(acc[f][n], af[f], bf[n]);
        }
        __syncthreads();
    }

    // ---- epilogue ----
    #pragma unroll
    for (int f = 0; f < 4; f++) {
        int rr = m0 + wm + f * 16 + g;
        #pragma unroll
        for (int n = 0; n < 8; n++) {
            int gc = n0 + wn + n * 8 + 2 * t;
            float v0 = acc[f][n][0], v1 = acc[f][n][1];
            float v2 = acc[f][n][2], v3 = acc[f][n][3];
            if (EPI == 5) {
                if (n0 >= 3 * DMODEL) {
                    int cc = gc - 3 * DMODEL;
                    __half* G = (__half*)aux;
                    *(__half2*)(G + (size_t)rr * DMODEL + cc) =
                        __floats2half2_rn(sigmoid_f(v0), sigmoid_f(v1));
                    *(__half2*)(G + (size_t)(rr + 8) * DMODEL + cc) =
                        __floats2half2_rn(sigmoid_f(v2), sigmoid_f(v3));
                } else {
                    __half* Q = (__half*)Cv;
                    *(__half2*)(Q + (size_t)rr * (3 * DMODEL) + gc)       = __floats2half2_rn(v0, v1);
                    *(__half2*)(Q + (size_t)(rr + 8) * (3 * DMODEL) + gc) = __floats2half2_rn(v2, v3);
                }
            } else if (EPI == 6) {
                int j = ((n0 + wn + n * 8) >> 1) + t;
                __half* C = (__half*)Cv;
                C[(size_t)rr * DFF + j]       = __float2half(v0 * sigmoid_f(v0) * v1);
                C[(size_t)(rr + 8) * DFF + j] = __float2half(v2 * sigmoid_f(v2) * v3);
            } else {  // EPI == 4
                size_t i0 = (size_t)rr * N + gc;
                size_t i1 = (size_t)(rr + 8) * N + gc;
                const float* ax = (const float*)aux;
                float2 x0 = *(const float2*)(ax + i0);
                float2 x1 = *(const float2*)(ax + i1);
                float* C = (float*)Cv;
                *(float2*)(C + i0) = make_float2(v0 + x0.x, v1 + x0.y);
                *(float2*)(C + i1) = make_float2(v2 + x1.x, v3 + x1.y);
            }
        }
    }
}

// ---------------------------------------------------------------------------
// Tensor-core flash attention, sliding window, fused gate (fp16).
// 256 threads / 8 warps, 128 q-rows per block, per-warp K-tile skipping,
// triple-buffered K/V (one barrier per tile).
// smem: Q[128x72h]=18432B | {K,V}[3 bufs][64x72h]=6x9216B. Total 73728B.
// ---------------------------------------------------------------------------
#define ATT_SMEM 73728

__global__ void __launch_bounds__(256) attn_mma_kernel(
    const __half* __restrict__ qkv, const __half* __restrict__ gate,
    __half* __restrict__ out)
{
    extern __shared__ __align__(16) unsigned char asm_[];
    uint32_t qbase = smem_u32(asm_);

    int tid = threadIdx.x;
    int warp = tid >> 5, lane = tid & 31;
    int g = lane >> 2, t = lane & 3;
    int b = blockIdx.y >> 4, h = blockIdx.y & 15;
    int q0 = blockIdx.x * 128;
    int wm16 = warp * 16;

    // stage Q tile [128 x 64]: 1024 quads, 4 per thread
    {
        int r = tid >> 1;
        int c = (tid & 1) * 4;
        const __half* src = qkv + ((size_t)(b * TSEQ + q0 + r)) * (3 * DMODEL) + h * DHEAD + c * 8;
        uint32_t dst = qbase + r * 144 + c * 16;
        #pragma unroll
        for (int j = 0; j < 4; j++) cp16(dst + j * 16, src + j * 8);
    }

    int s_lo = q0 - WINDOW;
    if (s_lo < 0) s_lo = 0;
    int nt = (q0 + 64 - s_lo) / 64 + 1;

    auto loadKV = [&](int s, int buf) {
        uint32_t kb = qbase + 18432 + buf * 18432;
        uint32_t vb = kb + 9216;
        int r = tid >> 2;
        int cq = (tid & 3) * 2;
        size_t base = ((size_t)(b * TSEQ + s + r)) * (3 * DMODEL) + h * DHEAD + cq * 8;
        uint32_t dK = kb + r * 144 + cq * 16;
        uint32_t dV = vb + r * 144 + cq * 16;
        #pragma unroll
        for (int j = 0; j < 2; j++) {
            cp16(dK + j * 16, qkv + base + DMODEL + j * 8);
            cp16(dV + j * 16, qkv + base + 2 * DMODEL + j * 8);
        }
    };

    // prologue: Q + tile 0 in one group
    loadKV(s_lo, 0);
    CP_COMMIT();

    int la_r = (lane & 7) + ((lane >> 3) & 1) * 8;
    int la_c = ((lane >> 4) & 1) * 8;
    int lb_r = (lane & 7) + ((lane >> 4) & 1) * 8;
    int lb_c = ((lane >> 3) & 1) * 8;

    uint32_t qf[4][4];
    float oacc[8][4];
    #pragma unroll
    for (int n = 0; n < 8; n++)
        #pragma unroll
        for (int i = 0; i < 4; i++) oacc[n][i] = 0.0f;
    float m0 = -1e30f, m1 = -1e30f, l0 = 0.0f, l1 = 0.0f;
    int qi0 = q0 + wm16 + g;
    int qi1 = qi0 + 8;
    int w_lo = q0 + wm16;
    int w_hi = w_lo + 15;

    int buf = 0;
    for (int it = 0; it < nt; it++) {
        int s = s_lo + it * 64;
        if (it + 1 < nt) {
            int nb = buf + 1 == 3 ? 0 : buf + 1;
            loadKV(s + 64, nb);
            CP_COMMIT();
            CP_WAIT(1);
        } else {
            CP_WAIT(0);
        }
        __syncthreads();

        if (it == 0) {
            #pragma unroll
            for (int ks = 0; ks < 4; ks++) {
                uint32_t addr = qbase + ((wm16 + la_r) * 72 + ks * 16 + la_c) * 2;
                ldsm4(qf[ks][0], qf[ks][1], qf[ks][2], qf[ks][3], addr);
            }
        }

        uint32_t kbase = qbase + 18432 + buf * 18432;
        uint32_t vbase = kbase + 9216;
        buf = buf + 1 == 3 ? 0 : buf + 1;

        // per-warp tile skip
        if (s > w_hi || s + 63 < w_lo - (WINDOW - 1)) continue;

        float sacc[8][4];
        #pragma unroll
        for (int n = 0; n < 8; n++)
            #pragma unroll
            for (int i = 0; i < 4; i++) sacc[n][i] = 0.0f;

        #pragma unroll
        for (int ks = 0; ks < 4; ks++) {
            uint32_t bf[8][2];
            #pragma unroll
            for (int np = 0; np < 4; np++) {
                uint32_t addr = kbase + ((np * 16 + lb_r) * 72 + ks * 16 + lb_c) * 2;
                ldsm4(bf[2 * np][0], bf[2 * np][1],
                      bf[2 * np + 1][0], bf[2 * np + 1][1], addr);
            }
            #pragma unroll
            for (int nf = 0; nf < 8; nf++)
                mma_f16(sacc[nf], qf[ks], bf[nf]);
        }

        float mt0 = -1e30f, mt1 = -1e30f;
        #pragma unroll
        for (int nf = 0; nf < 8; nf++) {
            int key = s + nf * 8 + 2 * t;
            #pragma unroll
            for (int c = 0; c < 2; c++) {
                unsigned d0 = (unsigned)(qi0 - (key + c));
                unsigned d1 = (unsigned)(qi1 - (key + c));
                float v0 = (d0 < (unsigned)WINDOW) ? sacc[nf][c] * 0.125f : -1e30f;
                float v1 = (d1 < (unsigned)WINDOW) ? sacc[nf][c + 2] * 0.125f : -1e30f;
                sacc[nf][c] = v0; sacc[nf][c + 2] = v1;
                mt0 = fmaxf(mt0, v0); mt1 = fmaxf(mt1, v1);
            }
        }
        mt0 = fmaxf(mt0, __shfl_xor_sync(0xffffffffu, mt0, 1));
        mt0 = fmaxf(mt0, __shfl_xor_sync(0xffffffffu, mt0, 2));
        mt1 = fmaxf(mt1, __shfl_xor_sync(0xffffffffu, mt1, 1));
        mt1 = fmaxf(mt1, __shfl_xor_sync(0xffffffffu, mt1, 2));

        float mn0 = fmaxf(m0, mt0), mn1 = fmaxf(m1, mt1);
        float cor0 = __expf(m0 - mn0), cor1 = __expf(m1 - mn1);
        m0 = mn0; m1 = mn1;
        l0 *= cor0; l1 *= cor1;
        #pragma unroll
        for (int nf = 0; nf < 8; nf++) {
            oacc[nf][0] *= cor0; oacc[nf][1] *= cor0;
            oacc[nf][2] *= cor1; oacc[nf][3] *= cor1;
        }
        float ps0 = 0.0f, ps1 = 0.0f;
        #pragma unroll
        for (int nf = 0; nf < 8; nf++) {
            #pragma unroll
            for (int c = 0; c < 2; c++) {
                float p0 = __expf(sacc[nf][c] - m0);
                float p1 = __expf(sacc[nf][c + 2] - m1);
                sacc[nf][c] = p0; sacc[nf][c + 2] = p1;
                ps0 += p0; ps1 += p1;
            }
        }
        l0 += ps0; l1 += ps1;

        #pragma unroll
        for (int kc = 0; kc < 4; kc++) {
            uint32_t pf[4];
            pf[0] = packh2(sacc[2 * kc][0],     sacc[2 * kc][1]);
            pf[1] = packh2(sacc[2 * kc][2],     sacc[2 * kc][3]);
            pf[2] = packh2(sacc[2 * kc + 1][0], sacc[2 * kc + 1][1]);
            pf[3] = packh2(sacc[2 * kc + 1][2], sacc[2 * kc + 1][3]);
            #pragma unroll
            for (int dp = 0; dp < 4; dp++) {
                uint32_t addr = vbase + ((kc * 16 + la_r) * 72 + dp * 16 + la_c) * 2;
                uint32_t v0, v1, v2, v3;
                ldsm4t(v0, v1, v2, v3, addr);
                uint32_t bb0[2] = { v0, v1 };
                uint32_t bb1[2] = { v2, v3 };
                mma_f16(oacc[2 * dp], pf, bb0);
                mma_f16(oacc[2 * dp + 1], pf, bb1);
            }
        }
    }

    l0 += __shfl_xor_sync(0xffffffffu, l0, 1);
    l0 += __shfl_xor_sync(0xffffffffu, l0, 2);
    l1 += __shfl_xor_sync(0xffffffffu, l1, 1);
    l1 += __shfl_xor_sync(0xffffffffu, l1, 2);
    float inv0 = 1.0f / l0, inv1 = 1.0f / l1;

    size_t tq0 = (size_t)b * TSEQ + qi0;
    size_t tq1 = tq0 + 8;
    #pragma unroll
    for (int nf = 0; nf < 8; nf++) {
        int col = h * DHEAD + nf * 8 + 2 * t;
        float2 g0 = __half22float2(*(const __half2*)(gate + tq0 * DMODEL + col));
        float2 g1 = __half22float2(*(const __half2*)(gate + tq1 * DMODEL + col));
        *(__half2*)(out + tq0 * DMODEL + col) =
            __floats2half2_rn(oacc[nf][0] * inv0 * g0.x, oacc[nf][1] * inv0 * g0.y);
        *(__half2*)(out + tq1 * DMODEL + col) =
            __floats2half2_rn(oacc[nf][2] * inv1 * g1.x, oacc[nf][3] * inv1 * g1.y);
    }
}

// ---------------------------------------------------------------------------
// Launch
// ---------------------------------------------------------------------------
extern "C" void kernel_launch(void* const* d_in, const int* in_sizes, int n_in,
                              void* d_out, int out_size)
{
    const float* x      = (const float*)d_in[0];
    const float* ln1_w  = (const float*)d_in[1];
    const float* qkv_w  = (const float*)d_in[2];
    const float* gate_w = (const float*)d_in[3];
    const float* out_w  = (const float*)d_in[4];
    const float* ln2_w  = (const float*)d_in[5];
    const float* wg     = (const float*)d_in[6];
    const float* wu     = (const float*)d_in[7];
    const float* wo     = (const float*)d_in[8];
    float* out = (float*)d_out;

    __half *xnh, *qkvh, *gateh, *attnh, *hnh, *ubh, *wqg, *wouth, *wfh, *woh;
    cudaGetSymbolAddress((void**)&xnh,   g_xn_h);
    cudaGetSymbolAddress((void**)&qkvh,  g_qkv_h);
    cudaGetSymbolAddress((void**)&gateh, g_gate_h);
    cudaGetSymbolAddress((void**)&attnh, g_attn_h);
    cudaGetSymbolAddress((void**)&hnh,   g_hn_h);
    cudaGetSymbolAddress((void**)&ubh,   g_u_h);
    cudaGetSymbolAddress((void**)&wqg,   g_wqg);
    cudaGetSymbolAddress((void**)&wouth, g_wout);
    cudaGetSymbolAddress((void**)&wfh,   g_wf);
    cudaGetSymbolAddress((void**)&woh,   g_wo);

    cudaFuncSetAttribute(gemm_h<4>, cudaFuncAttributeMaxDynamicSharedMemorySize, GSMEM);
    cudaFuncSetAttribute(gemm_h<5>, cudaFuncAttributeMaxDynamicSharedMemorySize, GSMEM);
    cudaFuncSetAttribute(gemm_h<6>, cudaFuncAttributeMaxDynamicSharedMemorySize, GSMEM);
    cudaFuncSetAttribute(attn_mma_kernel, cudaFuncAttributeMaxDynamicSharedMemorySize, ATT_SMEM);

    // 0+1. fused prologue: rmsnorm1 (blocks 0..4095) + all weights->fp16
    prologue_kernel<<<TOKENS + W2H_BLOCKS, 256>>>(
        x, ln1_w, xnh, qkv_w, gate_w, out_w, wg, wu, wo,
        wqg, wouth, wfh, woh);

    // 2+3. fused qkv|gate GEMM (BN=256): qkv -> fp16, gate -> sigmoid fp16
    gemm_h<5><<<dim3(4 * DMODEL / 256, TOKENS / 128), GTHREADS, GSMEM>>>(
        xnh, wqg, qkvh, gateh, TOKENS, 4 * DMODEL, DMODEL);

    // 4. attn (tensor-core flash, triple-buffered K/V) -> fp16
    attn_mma_kernel<<<dim3(TSEQ / 128, 2 * NHEADS), 256, ATT_SMEM>>>(qkvh, gateh, attnh);

    // 5. x1 = x + attn @ out_w^T -> d_out (fp32)
    gemm_h<4><<<dim3(DMODEL / 256, TOKENS / 128), GTHREADS, GSMEM>>>(
        attnh, wouth, out, x, TOKENS, DMODEL, DMODEL);

    // 6. hn = rmsnorm(x1, ln2_w) -> fp16
    rmsnorm_kernel<<<TOKENS, 256>>>(out, ln2_w, hnh);

    // 7+8. fused FFN: ub = silu(hn@wg^T) * (hn@wu^T) -> fp16 (interleaved B)
    gemm_h<6><<<dim3(2 * DFF / 256, TOKENS / 128), GTHREADS, GSMEM>>>(
        hnh, wfh, ubh, nullptr, TOKENS, 2 * DFF, DMODEL);

    // 9. out = x1 + ub @ wo^T (in-place residual on d_out)
    gemm_h<4><<<dim3(DMODEL / 256, TOKENS / 128), GTHREADS, GSMEM>>>(
        ubh, woh, out, out, TOKENS, DMODEL, DFF);
}